// round 1
// baseline (speedup 1.0000x reference)
#include <cuda_runtime.h>

// Problem dims
#define BATCH   8
#define SEQ     2048
#define DIN     1024
#define DHEAD   64
#define BS_TOT  (BATCH * SEQ)       // 16384

// Scratch for projected q (pre-scaled by 1/sqrt(64)), k, v. 3 x 4 MB.
__device__ float g_q[BS_TOT * DHEAD];
__device__ float g_k[BS_TOT * DHEAD];
__device__ float g_v[BS_TOT * DHEAD];

// ---------------------------------------------------------------------------
// QKV projection: out = X[16384,1024] @ W[1024,64] + b   (q additionally * 0.125)
// BM=128, BN=64 (full), BK=16. 256 threads = 16x16, 8x4 microtile.
// X tile stored k-major (transposed) in smem so inner loop is pure ld.shared.v4.
// ---------------------------------------------------------------------------
__global__ __launch_bounds__(256) void qkv_kernel(
    const float* __restrict__ x,
    const float* __restrict__ Wq, const float* __restrict__ bq,
    const float* __restrict__ Wk, const float* __restrict__ bk,
    const float* __restrict__ Wv, const float* __restrict__ bv)
{
    const int t  = threadIdx.x;
    const int tx = t & 15;          // 0..15 -> 4 output cols
    const int ty = t >> 4;          // 0..15 -> 8 output rows
    const int m0 = blockIdx.x * 128;
    const int which = blockIdx.y;   // 0=q, 1=k, 2=v

    const float* __restrict__ W    = (which == 0) ? Wq : (which == 1) ? Wk : Wv;
    const float* __restrict__ bias = (which == 0) ? bq : (which == 1) ? bk : bv;
    float* __restrict__ outp       = (which == 0) ? g_q : (which == 1) ? g_k : g_v;
    const float scale = (which == 0) ? 0.125f : 1.0f;   // 1/sqrt(64) folded into q

    __shared__ float Xs[16][128];   // [k][row] (transposed)
    __shared__ float Ws[16][64];    // [k][col]

    float acc[8][4];
#pragma unroll
    for (int i = 0; i < 8; i++)
#pragma unroll
        for (int j = 0; j < 4; j++) acc[i][j] = 0.0f;

    for (int k0 = 0; k0 < DIN; k0 += 16) {
        // X tile: 128 rows x 16 k, loaded as float4 along k, stored transposed.
#pragma unroll
        for (int r = 0; r < 2; r++) {
            int idx = t + r * 256;            // 0..511
            int row = idx >> 2;               // 0..127
            int kg  = (idx & 3) * 4;          // 0,4,8,12
            float4 v4 = *(const float4*)&x[(m0 + row) * DIN + k0 + kg];
            Xs[kg + 0][row] = v4.x;
            Xs[kg + 1][row] = v4.y;
            Xs[kg + 2][row] = v4.z;
            Xs[kg + 3][row] = v4.w;
        }
        // W tile: 16 x 64, straight float4 copy.
        {
            int kk = t >> 4;                  // 0..15
            int c  = (t & 15) * 4;            // 0..60
            *(float4*)&Ws[kk][c] = *(const float4*)&W[(k0 + kk) * DHEAD + c];
        }
        __syncthreads();

#pragma unroll
        for (int kk = 0; kk < 16; kk++) {
            float4 a0 = *(const float4*)&Xs[kk][8 * ty];
            float4 a1 = *(const float4*)&Xs[kk][8 * ty + 4];
            float4 b4 = *(const float4*)&Ws[kk][4 * tx];
            float a[8] = {a0.x, a0.y, a0.z, a0.w, a1.x, a1.y, a1.z, a1.w};
            float bb[4] = {b4.x, b4.y, b4.z, b4.w};
#pragma unroll
            for (int i = 0; i < 8; i++)
#pragma unroll
                for (int j = 0; j < 4; j++)
                    acc[i][j] += a[i] * bb[j];
        }
        __syncthreads();
    }

    float4 bias4 = *(const float4*)&bias[4 * tx];
    float bb[4] = {bias4.x, bias4.y, bias4.z, bias4.w};
#pragma unroll
    for (int i = 0; i < 8; i++) {
        int row = m0 + 8 * ty + i;
        float4 o;
        o.x = (acc[i][0] + bb[0]) * scale;
        o.y = (acc[i][1] + bb[1]) * scale;
        o.z = (acc[i][2] + bb[2]) * scale;
        o.w = (acc[i][3] + bb[3]) * scale;
        *(float4*)&outp[row * DHEAD + 4 * tx] = o;
    }
}

// ---------------------------------------------------------------------------
// Flash attention: Br = Bc = 64, D = 64. One block per (q-tile, batch).
// 256 threads = 16x16, 4x4 microtiles for QK^T and PV.
// Q and K stored k-major in smem; P stored key-major (transposed) so both
// GEMM inner loops are pure aligned ld.shared.v4 with no bank conflicts.
// Softmax row stats reduced via shfl.xor within the 16-lane row group.
// Dynamic smem: 4 * 64*64 floats = 64 KB.
// ---------------------------------------------------------------------------
__global__ __launch_bounds__(256) void attn_kernel(float* __restrict__ out)
{
    extern __shared__ float smem[];
    float (*Qs)[64] = (float(*)[64])(smem);          // [c][qrow]  (transposed)
    float (*Ks)[64] = (float(*)[64])(smem + 4096);   // [c][key]   (transposed)
    float (*Vs)[64] = (float(*)[64])(smem + 8192);   // [key][c]
    float (*Ps)[64] = (float(*)[64])(smem + 12288);  // [key][qrow](transposed)

    const int t  = threadIdx.x;
    const int tx = t & 15;      // 4 cols
    const int ty = t >> 4;      // 4 rows
    const int qt = blockIdx.x;  // 0..31
    const int b  = blockIdx.y;  // 0..7
    const int qbase  = b * SEQ + qt * 64;
    const int kvbase = b * SEQ;

    // Load Q tile (already scaled by 1/8), transposed.
    {
        int row = t >> 2;             // 0..63
        int cg  = (t & 3) * 16;       // 0,16,32,48
#pragma unroll
        for (int u = 0; u < 4; u++) {
            float4 v4 = *(const float4*)&g_q[(qbase + row) * DHEAD + cg + 4 * u];
            int c = cg + 4 * u;
            Qs[c + 0][row] = v4.x;
            Qs[c + 1][row] = v4.y;
            Qs[c + 2][row] = v4.z;
            Qs[c + 3][row] = v4.w;
        }
    }

    float m[4], l[4], o[4][4];
#pragma unroll
    for (int i = 0; i < 4; i++) {
        m[i] = -3.0e38f;
        l[i] = 0.0f;
#pragma unroll
        for (int j = 0; j < 4; j++) o[i][j] = 0.0f;
    }

    for (int kt = 0; kt < SEQ / 64; kt++) {
        __syncthreads();   // prior iter's readers of Ks/Vs done (also covers Q load)

        // Load K tile (transposed) and V tile (direct).
        {
            int key = t >> 2;
            int cg  = (t & 3) * 16;
            const float* __restrict__ krow = &g_k[(kvbase + kt * 64 + key) * DHEAD];
            const float* __restrict__ vrow = &g_v[(kvbase + kt * 64 + key) * DHEAD];
#pragma unroll
            for (int u = 0; u < 4; u++) {
                int c = cg + 4 * u;
                float4 k4 = *(const float4*)&krow[c];
                Ks[c + 0][key] = k4.x;
                Ks[c + 1][key] = k4.y;
                Ks[c + 2][key] = k4.z;
                Ks[c + 3][key] = k4.w;
                *(float4*)&Vs[key][c] = *(const float4*)&vrow[c];
            }
        }
        __syncthreads();

        // S = Q K^T (scale pre-folded into Q).
        float acc[4][4];
#pragma unroll
        for (int i = 0; i < 4; i++)
#pragma unroll
            for (int j = 0; j < 4; j++) acc[i][j] = 0.0f;

#pragma unroll 8
        for (int k = 0; k < 64; k++) {
            float4 a4 = *(const float4*)&Qs[k][4 * ty];
            float4 b4 = *(const float4*)&Ks[k][4 * tx];
            float a[4] = {a4.x, a4.y, a4.z, a4.w};
            float bb[4] = {b4.x, b4.y, b4.z, b4.w};
#pragma unroll
            for (int i = 0; i < 4; i++)
#pragma unroll
                for (int j = 0; j < 4; j++)
                    acc[i][j] += a[i] * bb[j];
        }

        // Online softmax (stats shared across the 16 lanes owning each row).
#pragma unroll
        for (int i = 0; i < 4; i++) {
            float mx = acc[i][0];
#pragma unroll
            for (int j = 1; j < 4; j++) mx = fmaxf(mx, acc[i][j]);
#pragma unroll
            for (int sh = 1; sh < 16; sh <<= 1)
                mx = fmaxf(mx, __shfl_xor_sync(0xffffffffu, mx, sh));
            float mnew  = fmaxf(m[i], mx);
            float alpha = __expf(m[i] - mnew);
            float s = 0.0f;
#pragma unroll
            for (int j = 0; j < 4; j++) {
                float p = __expf(acc[i][j] - mnew);
                acc[i][j] = p;
                s += p;
            }
#pragma unroll
            for (int sh = 1; sh < 16; sh <<= 1)
                s += __shfl_xor_sync(0xffffffffu, s, sh);
            l[i] = l[i] * alpha + s;
            m[i] = mnew;
#pragma unroll
            for (int j = 0; j < 4; j++) o[i][j] *= alpha;
        }

        // Write P transposed: Ps[key][qrow]; 4 rows contiguous -> float4 store.
#pragma unroll
        for (int j = 0; j < 4; j++) {
            float4 p4 = make_float4(acc[0][j], acc[1][j], acc[2][j], acc[3][j]);
            *(float4*)&Ps[4 * tx + j][4 * ty] = p4;
        }
        __syncthreads();

        // O += P V
#pragma unroll 8
        for (int k = 0; k < 64; k++) {
            float4 a4 = *(const float4*)&Ps[k][4 * ty];
            float4 v4 = *(const float4*)&Vs[k][4 * tx];
            float a[4] = {a4.x, a4.y, a4.z, a4.w};
            float vv[4] = {v4.x, v4.y, v4.z, v4.w};
#pragma unroll
            for (int i = 0; i < 4; i++)
#pragma unroll
                for (int j = 0; j < 4; j++)
                    o[i][j] += a[i] * vv[j];
        }
    }

    // Normalize and write out.
#pragma unroll
    for (int i = 0; i < 4; i++) {
        float inv_l = 1.0f / l[i];
        int row = qbase + 4 * ty + i;
        float4 o4 = make_float4(o[i][0] * inv_l, o[i][1] * inv_l,
                                o[i][2] * inv_l, o[i][3] * inv_l);
        *(float4*)&out[row * DHEAD + 4 * tx] = o4;
    }
}

// ---------------------------------------------------------------------------
extern "C" void kernel_launch(void* const* d_in, const int* in_sizes, int n_in,
                              void* d_out, int out_size)
{
    const float* x  = (const float*)d_in[0];
    const float* Wq = (const float*)d_in[1];
    const float* bq = (const float*)d_in[2];
    const float* Wk = (const float*)d_in[3];
    const float* bk = (const float*)d_in[4];
    const float* Wv = (const float*)d_in[5];
    const float* bv = (const float*)d_in[6];
    float* out = (float*)d_out;

    (void)in_sizes; (void)n_in; (void)out_size;

    // 64 KB dynamic smem for the attention kernel (over the 48 KB default).
    cudaFuncSetAttribute(attn_kernel,
                         cudaFuncAttributeMaxDynamicSharedMemorySize, 65536);

    qkv_kernel<<<dim3(BS_TOT / 128, 3), 256>>>(x, Wq, bq, Wk, bk, Wv, bv);
    attn_kernel<<<dim3(SEQ / 64, BATCH), 256, 65536>>>(out);
}

// round 5
// speedup vs baseline: 1.7072x; 1.7072x over previous
#include <cuda_runtime.h>
#include <cuda_bf16.h>
#include <cstdint>

// Problem dims
#define BATCH   8
#define SEQ     2048
#define DIN     1024
#define DHEAD   64
#define BS_TOT  (BATCH * SEQ)       // 16384

// Projected q/k/v stored as split bf16 pairs (val = hi + lo), 2 MB each.
// q is pre-scaled by 1/sqrt(64).
__device__ __nv_bfloat16 g_qh[BS_TOT * DHEAD];
__device__ __nv_bfloat16 g_ql[BS_TOT * DHEAD];
__device__ __nv_bfloat16 g_kh[BS_TOT * DHEAD];
__device__ __nv_bfloat16 g_kl[BS_TOT * DHEAD];
__device__ __nv_bfloat16 g_vh[BS_TOT * DHEAD];
__device__ __nv_bfloat16 g_vl[BS_TOT * DHEAD];

// ---------------------------------------------------------------------------
// mma.sync m16n8k16 row.col bf16 -> f32 accumulate (sm_80+ PTX; compute_100 OK)
// ---------------------------------------------------------------------------
__device__ __forceinline__ void mma16816(float* d, const uint32_t* a,
                                         uint32_t b0, uint32_t b1) {
    asm volatile(
        "mma.sync.aligned.m16n8k16.row.col.f32.bf16.bf16.f32 "
        "{%0,%1,%2,%3}, {%4,%5,%6,%7}, {%8,%9}, {%0,%1,%2,%3};\n"
        : "+f"(d[0]), "+f"(d[1]), "+f"(d[2]), "+f"(d[3])
        : "r"(a[0]), "r"(a[1]), "r"(a[2]), "r"(a[3]), "r"(b0), "r"(b1));
}

__device__ __forceinline__ uint32_t pack2(float lo, float hi) {
    __nv_bfloat162 h = __floats2bfloat162_rn(lo, hi);   // lo -> lower 16 bits
    return *(uint32_t*)&h;
}

// ===========================================================================
// QKV projection: out = X[16384,1024] @ W[1024,64] + b  (q * 0.125)
// FFMA kernel (proven). Epilogue writes split bf16 (hi, lo) pairs.
// ===========================================================================
__global__ __launch_bounds__(256) void qkv_kernel(
    const float* __restrict__ x,
    const float* __restrict__ Wq, const float* __restrict__ bq,
    const float* __restrict__ Wk, const float* __restrict__ bk,
    const float* __restrict__ Wv, const float* __restrict__ bv)
{
    const int t  = threadIdx.x;
    const int tx = t & 15;
    const int ty = t >> 4;
    const int m0 = blockIdx.x * 128;
    const int which = blockIdx.y;

    const float* __restrict__ W    = (which == 0) ? Wq : (which == 1) ? Wk : Wv;
    const float* __restrict__ bias = (which == 0) ? bq : (which == 1) ? bk : bv;
    __nv_bfloat16* __restrict__ oh = (which == 0) ? g_qh : (which == 1) ? g_kh : g_vh;
    __nv_bfloat16* __restrict__ ol = (which == 0) ? g_ql : (which == 1) ? g_kl : g_vl;
    const float scale = (which == 0) ? 0.125f : 1.0f;

    __shared__ float Xs[16][128];
    __shared__ float Ws[16][64];

    float acc[8][4];
#pragma unroll
    for (int i = 0; i < 8; i++)
#pragma unroll
        for (int j = 0; j < 4; j++) acc[i][j] = 0.0f;

    for (int k0 = 0; k0 < DIN; k0 += 16) {
#pragma unroll
        for (int r = 0; r < 2; r++) {
            int idx = t + r * 256;
            int row = idx >> 2;
            int kg  = (idx & 3) * 4;
            float4 v4 = *(const float4*)&x[(m0 + row) * DIN + k0 + kg];
            Xs[kg + 0][row] = v4.x;
            Xs[kg + 1][row] = v4.y;
            Xs[kg + 2][row] = v4.z;
            Xs[kg + 3][row] = v4.w;
        }
        {
            int kk = t >> 4;
            int c  = (t & 15) * 4;
            *(float4*)&Ws[kk][c] = *(const float4*)&W[(k0 + kk) * DHEAD + c];
        }
        __syncthreads();

#pragma unroll
        for (int kk = 0; kk < 16; kk++) {
            float4 a0 = *(const float4*)&Xs[kk][8 * ty];
            float4 a1 = *(const float4*)&Xs[kk][8 * ty + 4];
            float4 b4 = *(const float4*)&Ws[kk][4 * tx];
            float a[8] = {a0.x, a0.y, a0.z, a0.w, a1.x, a1.y, a1.z, a1.w};
            float bb[4] = {b4.x, b4.y, b4.z, b4.w};
#pragma unroll
            for (int i = 0; i < 8; i++)
#pragma unroll
                for (int j = 0; j < 4; j++)
                    acc[i][j] += a[i] * bb[j];
        }
        __syncthreads();
    }

    float4 bias4 = *(const float4*)&bias[4 * tx];
    float bb[4] = {bias4.x, bias4.y, bias4.z, bias4.w};
#pragma unroll
    for (int i = 0; i < 8; i++) {
        int row = m0 + 8 * ty + i;
        float v[4];
#pragma unroll
        for (int j = 0; j < 4; j++) v[j] = (acc[i][j] + bb[j]) * scale;
        // split to (hi, lo) bf16 and store as 2x uint2 (4 bf16 = 8B each)
        uint32_t h01 = pack2(v[0], v[1]);
        uint32_t h23 = pack2(v[2], v[3]);
        __nv_bfloat162 hh01 = *(__nv_bfloat162*)&h01;
        __nv_bfloat162 hh23 = *(__nv_bfloat162*)&h23;
        float2 f01 = __bfloat1622float2(hh01);
        float2 f23 = __bfloat1622float2(hh23);
        uint32_t l01 = pack2(v[0] - f01.x, v[1] - f01.y);
        uint32_t l23 = pack2(v[2] - f23.x, v[3] - f23.y);
        uint2 hs = make_uint2(h01, h23);
        uint2 ls = make_uint2(l01, l23);
        *(uint2*)&oh[row * DHEAD + 4 * tx] = hs;
        *(uint2*)&ol[row * DHEAD + 4 * tx] = ls;
    }
}

// ===========================================================================
// Flash attention with warp-level mma.sync (bf16 split, 3 passes).
// Br=128 q-rows/CTA, Bc=64 keys/tile, 256 threads (8 warps).
// Warp w owns q-rows 16w..16w+15. Per tile:
//   S[16,64]  = Qh*Kh + Qh*Kl + Ql*Kh     (m16n8k16: 4 ktiles x 8 ntiles x 3)
//   PV[16,64] = Ph*Vh + Ph*Vl + Pl*Vh     (P frags built in registers from S)
// Online softmax per row; row stats reduced in aligned lane-quads.
// Smem: K and V^T tiles as bf16 hi/lo with 72-elem row pitch (conflict-free).
// ===========================================================================
#define KPITCH 72   // 64 + 8 pad bf16 -> 144B rows; banks (36r+w)%32 distinct

__global__ __launch_bounds__(256) void attn_kernel(float* __restrict__ out)
{
    __shared__ __nv_bfloat16 Kh[64 * KPITCH];
    __shared__ __nv_bfloat16 Kl[64 * KPITCH];
    __shared__ __nv_bfloat16 Vth[64 * KPITCH];   // [d][key]
    __shared__ __nv_bfloat16 Vtl[64 * KPITCH];

    const int t    = threadIdx.x;
    const int w    = t >> 5;
    const int lane = t & 31;
    const int g    = lane >> 2;      // 0..7  (row within fragment)
    const int qc   = lane & 3;       // 0..3  (col pair selector)

    const int qt = blockIdx.x;       // 0..15
    const int b  = blockIdx.y;       // 0..7
    const int qrow0  = b * SEQ + qt * 128;
    const int kvbase = b * SEQ;

    const int rlo = qrow0 + 16 * w + g;      // this lane's low q-row (global)
    const int rhi = rlo + 8;

    // ---- load Q fragments once (warp-invariant across all KV tiles) ----
    uint32_t qh[4][4], ql[4][4];
#pragma unroll
    for (int k4 = 0; k4 < 4; k4++) {
        int c = k4 * 16 + qc * 2;
        qh[k4][0] = *(const uint32_t*)&g_qh[rlo * DHEAD + c];
        qh[k4][1] = *(const uint32_t*)&g_qh[rhi * DHEAD + c];
        qh[k4][2] = *(const uint32_t*)&g_qh[rlo * DHEAD + c + 8];
        qh[k4][3] = *(const uint32_t*)&g_qh[rhi * DHEAD + c + 8];
        ql[k4][0] = *(const uint32_t*)&g_ql[rlo * DHEAD + c];
        ql[k4][1] = *(const uint32_t*)&g_ql[rhi * DHEAD + c];
        ql[k4][2] = *(const uint32_t*)&g_ql[rlo * DHEAD + c + 8];
        ql[k4][3] = *(const uint32_t*)&g_ql[rhi * DHEAD + c + 8];
    }

    float m_lo = -3.0e38f, m_hi = -3.0e38f, l_lo = 0.0f, l_hi = 0.0f;
    float oacc[8][4];
#pragma unroll
    for (int n = 0; n < 8; n++)
#pragma unroll
        for (int j = 0; j < 4; j++) oacc[n][j] = 0.0f;

    for (int kt = 0; kt < SEQ / 64; kt++) {
        __syncthreads();   // previous tile's LDS done before restage

        // ---- stage K tile rows (straight copy, 16 bf16 per thread) ----
        {
            int key = t >> 2;            // 0..63
            int seg = (t & 3) * 16;      // 0,16,32,48
            const int gofs = (kvbase + kt * 64 + key) * DHEAD + seg;
            *(uint4*)&Kh[key * KPITCH + seg]     = *(const uint4*)&g_kh[gofs];
            *(uint4*)&Kh[key * KPITCH + seg + 8] = *(const uint4*)&g_kh[gofs + 8];
            *(uint4*)&Kl[key * KPITCH + seg]     = *(const uint4*)&g_kl[gofs];
            *(uint4*)&Kl[key * KPITCH + seg + 8] = *(const uint4*)&g_kl[gofs + 8];
        }
        // ---- stage V^T tile (transpose via scalar stores) ----
        {
            int key = t >> 2;
            int ds  = (t & 3) * 16;
            const int gofs = (kvbase + kt * 64 + key) * DHEAD + ds;
            uint4 h0 = *(const uint4*)&g_vh[gofs];
            uint4 h1 = *(const uint4*)&g_vh[gofs + 8];
            uint4 l0 = *(const uint4*)&g_vl[gofs];
            uint4 l1 = *(const uint4*)&g_vl[gofs + 8];
            const __nv_bfloat16* hv = (const __nv_bfloat16*)&h0;   // 8 + 8
            const __nv_bfloat16* lv = (const __nv_bfloat16*)&l0;
#pragma unroll
            for (int i = 0; i < 8; i++) {
                Vth[(ds + i) * KPITCH + key] = hv[i];
                Vtl[(ds + i) * KPITCH + key] = lv[i];
            }
            const __nv_bfloat16* hv2 = (const __nv_bfloat16*)&h1;
            const __nv_bfloat16* lv2 = (const __nv_bfloat16*)&l1;
#pragma unroll
            for (int i = 0; i < 8; i++) {
                Vth[(ds + 8 + i) * KPITCH + key] = hv2[i];
                Vtl[(ds + 8 + i) * KPITCH + key] = lv2[i];
            }
        }
        __syncthreads();

        // ---- S = Q K^T (3-pass split) ----
        float sacc[8][4];
#pragma unroll
        for (int n = 0; n < 8; n++)
#pragma unroll
            for (int j = 0; j < 4; j++) sacc[n][j] = 0.0f;

#pragma unroll
        for (int k4 = 0; k4 < 4; k4++) {
#pragma unroll
            for (int n = 0; n < 8; n++) {
                int base = (n * 8 + g) * KPITCH + k4 * 16 + qc * 2;
                uint32_t bh0 = *(const uint32_t*)&Kh[base];
                uint32_t bh1 = *(const uint32_t*)&Kh[base + 8];
                uint32_t bl0 = *(const uint32_t*)&Kl[base];
                uint32_t bl1 = *(const uint32_t*)&Kl[base + 8];
                mma16816(sacc[n], qh[k4], bh0, bh1);
                mma16816(sacc[n], qh[k4], bl0, bl1);
                mma16816(sacc[n], ql[k4], bh0, bh1);
            }
        }

        // ---- online softmax (rows rlo: c0/c1, rhi: c2/c3) ----
        float tl = -3.0e38f, th = -3.0e38f;
#pragma unroll
        for (int n = 0; n < 8; n++) {
            tl = fmaxf(tl, fmaxf(sacc[n][0], sacc[n][1]));
            th = fmaxf(th, fmaxf(sacc[n][2], sacc[n][3]));
        }
        tl = fmaxf(tl, __shfl_xor_sync(0xffffffffu, tl, 1));
        tl = fmaxf(tl, __shfl_xor_sync(0xffffffffu, tl, 2));
        th = fmaxf(th, __shfl_xor_sync(0xffffffffu, th, 1));
        th = fmaxf(th, __shfl_xor_sync(0xffffffffu, th, 2));

        float mn_lo = fmaxf(m_lo, tl);
        float mn_hi = fmaxf(m_hi, th);
        float al_lo = __expf(m_lo - mn_lo);
        float al_hi = __expf(m_hi - mn_hi);
        m_lo = mn_lo; m_hi = mn_hi;

        float slo = 0.0f, shi = 0.0f;
#pragma unroll
        for (int n = 0; n < 8; n++) {
            float e0 = __expf(sacc[n][0] - mn_lo);
            float e1 = __expf(sacc[n][1] - mn_lo);
            float e2 = __expf(sacc[n][2] - mn_hi);
            float e3 = __expf(sacc[n][3] - mn_hi);
            sacc[n][0] = e0; sacc[n][1] = e1; sacc[n][2] = e2; sacc[n][3] = e3;
            slo += e0 + e1; shi += e2 + e3;
        }
        slo += __shfl_xor_sync(0xffffffffu, slo, 1);
        slo += __shfl_xor_sync(0xffffffffu, slo, 2);
        shi += __shfl_xor_sync(0xffffffffu, shi, 1);
        shi += __shfl_xor_sync(0xffffffffu, shi, 2);
        l_lo = l_lo * al_lo + slo;
        l_hi = l_hi * al_hi + shi;

#pragma unroll
        for (int n = 0; n < 8; n++) {
            oacc[n][0] *= al_lo; oacc[n][1] *= al_lo;
            oacc[n][2] *= al_hi; oacc[n][3] *= al_hi;
        }

        // ---- PV: O += P V (P frags built in regs from sacc) ----
#pragma unroll
        for (int pk = 0; pk < 4; pk++) {
            uint32_t pah[4], pal[4];
#pragma unroll
            for (int half = 0; half < 2; half++) {       // keys base / base+8
                float e0 = sacc[2 * pk + half][0];
                float e1 = sacc[2 * pk + half][1];
                float e2 = sacc[2 * pk + half][2];
                float e3 = sacc[2 * pk + half][3];
                uint32_t h01 = pack2(e0, e1);
                uint32_t h23 = pack2(e2, e3);
                float2 f01 = __bfloat1622float2(*(__nv_bfloat162*)&h01);
                float2 f23 = __bfloat1622float2(*(__nv_bfloat162*)&h23);
                pah[0 + 2 * half] = h01;                 // a0/a2: row_lo
                pah[1 + 2 * half] = h23;                 // a1/a3: row_hi
                pal[0 + 2 * half] = pack2(e0 - f01.x, e1 - f01.y);
                pal[1 + 2 * half] = pack2(e2 - f23.x, e3 - f23.y);
            }
#pragma unroll
            for (int n = 0; n < 8; n++) {
                int base = (n * 8 + g) * KPITCH + pk * 16 + qc * 2;
                uint32_t bh0 = *(const uint32_t*)&Vth[base];
                uint32_t bh1 = *(const uint32_t*)&Vth[base + 8];
                uint32_t bl0 = *(const uint32_t*)&Vtl[base];
                uint32_t bl1 = *(const uint32_t*)&Vtl[base + 8];
                mma16816(oacc[n], pah, bh0, bh1);
                mma16816(oacc[n], pah, bl0, bl1);
                mma16816(oacc[n], pal, bh0, bh1);
            }
        }
    }

    // ---- epilogue: normalize + store fp32 ----
    const float il = 1.0f / l_lo;
    const float ih = 1.0f / l_hi;
#pragma unroll
    for (int n = 0; n < 8; n++) {
        int c = n * 8 + qc * 2;
        float2 v0 = make_float2(oacc[n][0] * il, oacc[n][1] * il);
        float2 v1 = make_float2(oacc[n][2] * ih, oacc[n][3] * ih);
        *(float2*)&out[rlo * DHEAD + c] = v0;
        *(float2*)&out[rhi * DHEAD + c] = v1;
    }
}

// ===========================================================================
extern "C" void kernel_launch(void* const* d_in, const int* in_sizes, int n_in,
                              void* d_out, int out_size)
{
    const float* x  = (const float*)d_in[0];
    const float* Wq = (const float*)d_in[1];
    const float* bq = (const float*)d_in[2];
    const float* Wk = (const float*)d_in[3];
    const float* bk = (const float*)d_in[4];
    const float* Wv = (const float*)d_in[5];
    const float* bv = (const float*)d_in[6];
    float* out = (float*)d_out;

    (void)in_sizes; (void)n_in; (void)out_size;

    qkv_kernel<<<dim3(BS_TOT / 128, 3), 256>>>(x, Wq, bq, Wk, bk, Wv, bv);
    attn_kernel<<<dim3(SEQ / 128, BATCH), 256>>>(out);
}

// round 6
// speedup vs baseline: 2.3078x; 1.3518x over previous
#include <cuda_runtime.h>
#include <cuda_bf16.h>
#include <cstdint>

// Problem dims
#define BATCH   8
#define SEQ     2048
#define DIN     1024
#define DHEAD   64
#define BS_TOT  (BATCH * SEQ)       // 16384

// Projected q/k/v as split bf16 pairs (val = hi + lo), q pre-scaled by 0.125.
__device__ __nv_bfloat16 g_qh[BS_TOT * DHEAD];
__device__ __nv_bfloat16 g_ql[BS_TOT * DHEAD];
__device__ __nv_bfloat16 g_kh[BS_TOT * DHEAD];
__device__ __nv_bfloat16 g_kl[BS_TOT * DHEAD];
__device__ __nv_bfloat16 g_vh[BS_TOT * DHEAD];
__device__ __nv_bfloat16 g_vl[BS_TOT * DHEAD];

// ---------------------------------------------------------------------------
// PTX helpers (all sm_80-era: compile fine at compute_100)
// ---------------------------------------------------------------------------
__device__ __forceinline__ uint32_t smem_u32(const void* p) {
    uint32_t a;
    asm("{ .reg .u64 t; cvta.to.shared.u64 t, %1; cvt.u32.u64 %0, t; }" : "=r"(a) : "l"(p));
    return a;
}
__device__ __forceinline__ void mma16816(float* d, const uint32_t* a,
                                         uint32_t b0, uint32_t b1) {
    asm volatile(
        "mma.sync.aligned.m16n8k16.row.col.f32.bf16.bf16.f32 "
        "{%0,%1,%2,%3}, {%4,%5,%6,%7}, {%8,%9}, {%0,%1,%2,%3};\n"
        : "+f"(d[0]), "+f"(d[1]), "+f"(d[2]), "+f"(d[3])
        : "r"(a[0]), "r"(a[1]), "r"(a[2]), "r"(a[3]), "r"(b0), "r"(b1));
}
__device__ __forceinline__ void ldmx4(uint32_t* r, uint32_t addr) {
    asm volatile("ldmatrix.sync.aligned.m8n8.x4.shared.b16 {%0,%1,%2,%3}, [%4];"
                 : "=r"(r[0]), "=r"(r[1]), "=r"(r[2]), "=r"(r[3]) : "r"(addr));
}
__device__ __forceinline__ void ldmx2t(uint32_t& r0, uint32_t& r1, uint32_t addr) {
    asm volatile("ldmatrix.sync.aligned.m8n8.x2.trans.shared.b16 {%0,%1}, [%2];"
                 : "=r"(r0), "=r"(r1) : "r"(addr));
}
__device__ __forceinline__ void cp16(uint32_t dst, const void* src) {
    asm volatile("cp.async.ca.shared.global [%0], [%1], 16;" :: "r"(dst), "l"(src));
}
__device__ __forceinline__ void cp_commit() {
    asm volatile("cp.async.commit_group;");
}
template <int N> __device__ __forceinline__ void cp_wait() {
    asm volatile("cp.async.wait_group %0;" :: "n"(N));
}
__device__ __forceinline__ uint32_t pack2(float a, float b) {
    __nv_bfloat162 h = __floats2bfloat162_rn(a, b);   // a -> lower 16 bits
    return *(uint32_t*)&h;
}
// split float4 into packed bf16 hi (2x uint32) and lo
__device__ __forceinline__ void split4(float4 v, uint2& hi, uint2& lo) {
    uint32_t h01 = pack2(v.x, v.y), h23 = pack2(v.z, v.w);
    float2 f01 = __bfloat1622float2(*(__nv_bfloat162*)&h01);
    float2 f23 = __bfloat1622float2(*(__nv_bfloat162*)&h23);
    hi.x = h01; hi.y = h23;
    lo.x = pack2(v.x - f01.x, v.y - f01.y);
    lo.y = pack2(v.z - f23.x, v.w - f23.y);
}

// ===========================================================================
// Fused QKV projection with mma.sync split-bf16 (3-pass hh+hl+lh).
// out[:,0:64]=q*0.125, [64:128]=k, [128:192]=v.  M=16384, N=192, K=1024.
// 256 CTAs x 128 thr; CTA: 64 rows; warp w: rows 16w..16w+15, all 192 cols.
// K-loop: 16 chunks of 64; X and W staged as bf16 hi/lo in smem each chunk.
// A-frags: ldmatrix.x4 (X row-major). B-frags: ldmatrix.x2.trans (W k-major).
// ===========================================================================
#define XP 72           // X smem pitch (elems)
#define WPIT 200        // W smem pitch (elems)
#define QKV_XH 0
#define QKV_XL 4608     // 64*72
#define QKV_WH 9216
#define QKV_WL 22016    // 9216 + 64*200
#define QKV_SMEM_ELEMS 34816
#define QKV_SMEM_BYTES (QKV_SMEM_ELEMS * 2)

__global__ __launch_bounds__(128, 2) void qkv_kernel(
    const float* __restrict__ x,
    const float* __restrict__ Wq, const float* __restrict__ bq,
    const float* __restrict__ Wk, const float* __restrict__ bk,
    const float* __restrict__ Wv, const float* __restrict__ bv)
{
    extern __shared__ __nv_bfloat16 smq[];
    const uint32_t sbase = smem_u32(smq);

    const int t    = threadIdx.x;
    const int w    = t >> 5;
    const int lane = t & 31;
    const int g    = lane >> 2;
    const int qc   = lane & 3;
    const int m0   = blockIdx.x * 64;
    const int wm   = w * 16;               // warp's row base within tile

    float acc[24][4];
#pragma unroll
    for (int f = 0; f < 24; f++)
#pragma unroll
        for (int j = 0; j < 4; j++) acc[f][j] = 0.0f;

    const int srow = t >> 1;               // staging row 0..63

    for (int k0 = 0; k0 < DIN; k0 += 64) {
        // ---- stage X chunk [64 rows x 64 k] as hi/lo bf16 ----
        {
            int ks = (t & 1) * 32;
            const float* xr = &x[(m0 + srow) * DIN + k0 + ks];
#pragma unroll
            for (int j = 0; j < 8; j++) {
                float4 v4 = *(const float4*)&xr[j * 4];
                uint2 hi, lo; split4(v4, hi, lo);
                int eo = srow * XP + ks + j * 4;
                *(uint2*)&smq[QKV_XH + eo] = hi;
                *(uint2*)&smq[QKV_XL + eo] = lo;
            }
        }
        // ---- stage W chunk [64 k x 192 n] as hi/lo bf16 ----
        {
            int cs = (t & 1) * 96;
#pragma unroll
            for (int j = 0; j < 24; j++) {
                int c   = cs + j * 4;
                int arr = c >> 6;
                int cc  = c & 63;
                const float* Wa = (arr == 0) ? Wq : (arr == 1) ? Wk : Wv;
                float4 v4 = *(const float4*)&Wa[(k0 + srow) * DHEAD + cc];
                uint2 hi, lo; split4(v4, hi, lo);
                int eo = srow * WPIT + c;
                *(uint2*)&smq[QKV_WH + eo] = hi;
                *(uint2*)&smq[QKV_WL + eo] = lo;
            }
        }
        __syncthreads();

        // ---- MMAs ----
#pragma unroll
        for (int k4 = 0; k4 < 4; k4++) {
            // A frags (hi, lo) via ldmatrix.x4
            int ar = wm + (lane & 7) + ((lane >> 3) & 1) * 8;
            int ac = k4 * 16 + (lane >> 4) * 8;
            uint32_t ah[4], al[4];
            ldmx4(ah, sbase + (uint32_t)(QKV_XH + ar * XP + ac) * 2);
            ldmx4(al, sbase + (uint32_t)(QKV_XL + ar * XP + ac) * 2);
#pragma unroll
            for (int f = 0; f < 24; f++) {
                int krow = k4 * 16 + (lane & 15);
                uint32_t baddr = (uint32_t)(krow * WPIT + f * 8) * 2;
                uint32_t bh0, bh1, bl0, bl1;
                ldmx2t(bh0, bh1, sbase + (uint32_t)QKV_WH * 2 + baddr);
                ldmx2t(bl0, bl1, sbase + (uint32_t)QKV_WL * 2 + baddr);
                mma16816(acc[f], ah, bh0, bh1);
                mma16816(acc[f], ah, bl0, bl1);
                mma16816(acc[f], al, bh0, bh1);
            }
        }
        __syncthreads();
    }

    // ---- epilogue: bias + scale, split to bf16 hi/lo, store ----
    const int rl = m0 + wm + g;
    const int rh = rl + 8;
#pragma unroll
    for (int f = 0; f < 24; f++) {
        int c   = f * 8 + 2 * qc;          // global col (even)
        int arr = c >> 6;
        int cc  = c & 63;
        const float* ba = (arr == 0) ? bq : (arr == 1) ? bk : bv;
        __nv_bfloat16* oh = (arr == 0) ? g_qh : (arr == 1) ? g_kh : g_vh;
        __nv_bfloat16* ol = (arr == 0) ? g_ql : (arr == 1) ? g_kl : g_vl;
        float s  = (arr == 0) ? 0.125f : 1.0f;
        float b0 = ba[cc], b1 = ba[cc + 1];
        float v0 = (acc[f][0] + b0) * s, v1 = (acc[f][1] + b1) * s;
        float v2 = (acc[f][2] + b0) * s, v3 = (acc[f][3] + b1) * s;
        uint32_t h01 = pack2(v0, v1);
        uint32_t h23 = pack2(v2, v3);
        float2 f01 = __bfloat1622float2(*(__nv_bfloat162*)&h01);
        float2 f23 = __bfloat1622float2(*(__nv_bfloat162*)&h23);
        *(uint32_t*)&oh[rl * DHEAD + cc] = h01;
        *(uint32_t*)&ol[rl * DHEAD + cc] = pack2(v0 - f01.x, v1 - f01.y);
        *(uint32_t*)&oh[rh * DHEAD + cc] = h23;
        *(uint32_t*)&ol[rh * DHEAD + cc] = pack2(v2 - f23.x, v3 - f23.y);
    }
}

// ===========================================================================
// Flash attention, mma.sync split-bf16 (3-pass), cp.async double-buffered KV.
// Br=128 q-rows/CTA (8 warps x 16), Bc=64 keys/tile, grid 128.
// K and V staged row-major [key][d]/[key][head] as bf16 hi/lo via cp.async;
// QK B-frags: direct LDS.32 (proven); PV B-frags: ldmatrix.x2.trans on V.
// ===========================================================================
#define KP 72
#define TILE_ELEMS (64 * KP)               // 4608
#define ABASE(arr, buf) (((arr) * 2 + (buf)) * TILE_ELEMS)
#define ATTN_SMEM_BYTES (8 * TILE_ELEMS * 2)   // 73728

__global__ __launch_bounds__(256) void attn_kernel(float* __restrict__ out)
{
    extern __shared__ __nv_bfloat16 sma[];
    const uint32_t sbase = smem_u32(sma);

    const int t    = threadIdx.x;
    const int w    = t >> 5;
    const int lane = t & 31;
    const int g    = lane >> 2;
    const int qc   = lane & 3;

    const int qt = blockIdx.x;             // 0..15
    const int b  = blockIdx.y;             // 0..7
    const int qrow0  = b * SEQ + qt * 128;
    const int kvbase = b * SEQ;

    const int rlo = qrow0 + 16 * w + g;
    const int rhi = rlo + 8;

    const __nv_bfloat16* gsrc[4] = {g_kh, g_kl, g_vh, g_vl};

    // issue tile 0 loads into buf 0
    {
        int row = (t & 255) >> 2;          // reuse t; 2 cps per array per thread
#pragma unroll
        for (int arr = 0; arr < 4; arr++) {
#pragma unroll
            for (int rep = 0; rep < 2; rep++) {
                int i   = t + rep * 256;   // 0..511
                int r   = i >> 3;
                int seg = (i & 7) * 8;
                cp16(sbase + (uint32_t)(ABASE(arr, 0) + r * KP + seg) * 2,
                     gsrc[arr] + (kvbase + r) * DHEAD + seg);
            }
        }
        (void)row;
    }
    cp_commit();

    // ---- Q fragments once (warp-invariant across KV tiles) ----
    uint32_t qh[4][4], ql[4][4];
#pragma unroll
    for (int k4 = 0; k4 < 4; k4++) {
        int c = k4 * 16 + qc * 2;
        qh[k4][0] = *(const uint32_t*)&g_qh[rlo * DHEAD + c];
        qh[k4][1] = *(const uint32_t*)&g_qh[rhi * DHEAD + c];
        qh[k4][2] = *(const uint32_t*)&g_qh[rlo * DHEAD + c + 8];
        qh[k4][3] = *(const uint32_t*)&g_qh[rhi * DHEAD + c + 8];
        ql[k4][0] = *(const uint32_t*)&g_ql[rlo * DHEAD + c];
        ql[k4][1] = *(const uint32_t*)&g_ql[rhi * DHEAD + c];
        ql[k4][2] = *(const uint32_t*)&g_ql[rlo * DHEAD + c + 8];
        ql[k4][3] = *(const uint32_t*)&g_ql[rhi * DHEAD + c + 8];
    }

    float m_lo = -3.0e38f, m_hi = -3.0e38f, l_lo = 0.0f, l_hi = 0.0f;
    float oacc[8][4];
#pragma unroll
    for (int n = 0; n < 8; n++)
#pragma unroll
        for (int j = 0; j < 4; j++) oacc[n][j] = 0.0f;

    for (int kt = 0; kt < SEQ / 64; kt++) {
        const int buf = kt & 1;

        // prefetch next tile into the other buffer
        if (kt < SEQ / 64 - 1) {
            const int nb = buf ^ 1;
            const int krow0 = kvbase + (kt + 1) * 64;
#pragma unroll
            for (int arr = 0; arr < 4; arr++) {
#pragma unroll
                for (int rep = 0; rep < 2; rep++) {
                    int i   = t + rep * 256;
                    int r   = i >> 3;
                    int seg = (i & 7) * 8;
                    cp16(sbase + (uint32_t)(ABASE(arr, nb) + r * KP + seg) * 2,
                         gsrc[arr] + (krow0 + r) * DHEAD + seg);
                }
            }
            cp_commit();
            cp_wait<1>();
        } else {
            cp_wait<0>();
        }
        __syncthreads();

        const __nv_bfloat16* Kh = sma + ABASE(0, buf);
        const __nv_bfloat16* Kl = sma + ABASE(1, buf);
        const uint32_t vh_b = sbase + (uint32_t)ABASE(2, buf) * 2;
        const uint32_t vl_b = sbase + (uint32_t)ABASE(3, buf) * 2;

        // ---- S = Q K^T (3-pass split) ----
        float sacc[8][4];
#pragma unroll
        for (int n = 0; n < 8; n++)
#pragma unroll
            for (int j = 0; j < 4; j++) sacc[n][j] = 0.0f;

#pragma unroll
        for (int k4 = 0; k4 < 4; k4++) {
#pragma unroll
            for (int n = 0; n < 8; n++) {
                int base = (n * 8 + g) * KP + k4 * 16 + qc * 2;
                uint32_t bh0 = *(const uint32_t*)&Kh[base];
                uint32_t bh1 = *(const uint32_t*)&Kh[base + 8];
                uint32_t bl0 = *(const uint32_t*)&Kl[base];
                uint32_t bl1 = *(const uint32_t*)&Kl[base + 8];
                mma16816(sacc[n], qh[k4], bh0, bh1);
                mma16816(sacc[n], qh[k4], bl0, bl1);
                mma16816(sacc[n], ql[k4], bh0, bh1);
            }
        }

        // ---- online softmax (rows rlo: c0/c1, rhi: c2/c3) ----
        float tl = -3.0e38f, th = -3.0e38f;
#pragma unroll
        for (int n = 0; n < 8; n++) {
            tl = fmaxf(tl, fmaxf(sacc[n][0], sacc[n][1]));
            th = fmaxf(th, fmaxf(sacc[n][2], sacc[n][3]));
        }
        tl = fmaxf(tl, __shfl_xor_sync(0xffffffffu, tl, 1));
        tl = fmaxf(tl, __shfl_xor_sync(0xffffffffu, tl, 2));
        th = fmaxf(th, __shfl_xor_sync(0xffffffffu, th, 1));
        th = fmaxf(th, __shfl_xor_sync(0xffffffffu, th, 2));

        float mn_lo = fmaxf(m_lo, tl);
        float mn_hi = fmaxf(m_hi, th);
        float al_lo = __expf(m_lo - mn_lo);
        float al_hi = __expf(m_hi - mn_hi);
        m_lo = mn_lo; m_hi = mn_hi;

        float slo = 0.0f, shi = 0.0f;
#pragma unroll
        for (int n = 0; n < 8; n++) {
            float e0 = __expf(sacc[n][0] - mn_lo);
            float e1 = __expf(sacc[n][1] - mn_lo);
            float e2 = __expf(sacc[n][2] - mn_hi);
            float e3 = __expf(sacc[n][3] - mn_hi);
            sacc[n][0] = e0; sacc[n][1] = e1; sacc[n][2] = e2; sacc[n][3] = e3;
            slo += e0 + e1; shi += e2 + e3;
        }
        slo += __shfl_xor_sync(0xffffffffu, slo, 1);
        slo += __shfl_xor_sync(0xffffffffu, slo, 2);
        shi += __shfl_xor_sync(0xffffffffu, shi, 1);
        shi += __shfl_xor_sync(0xffffffffu, shi, 2);
        l_lo = l_lo * al_lo + slo;
        l_hi = l_hi * al_hi + shi;

#pragma unroll
        for (int n = 0; n < 8; n++) {
            oacc[n][0] *= al_lo; oacc[n][1] *= al_lo;
            oacc[n][2] *= al_hi; oacc[n][3] *= al_hi;
        }

        // ---- PV: O += P V (P frags in regs; V B-frags via ldmatrix.trans) ----
#pragma unroll
        for (int pk = 0; pk < 4; pk++) {
            uint32_t pah[4], pal[4];
#pragma unroll
            for (int half = 0; half < 2; half++) {
                float e0 = sacc[2 * pk + half][0];
                float e1 = sacc[2 * pk + half][1];
                float e2 = sacc[2 * pk + half][2];
                float e3 = sacc[2 * pk + half][3];
                uint32_t h01 = pack2(e0, e1);
                uint32_t h23 = pack2(e2, e3);
                float2 f01 = __bfloat1622float2(*(__nv_bfloat162*)&h01);
                float2 f23 = __bfloat1622float2(*(__nv_bfloat162*)&h23);
                pah[0 + 2 * half] = h01;
                pah[1 + 2 * half] = h23;
                pal[0 + 2 * half] = pack2(e0 - f01.x, e1 - f01.y);
                pal[1 + 2 * half] = pack2(e2 - f23.x, e3 - f23.y);
            }
            const uint32_t krow = (uint32_t)(pk * 16 + (lane & 15));
#pragma unroll
            for (int n = 0; n < 8; n++) {
                uint32_t off = (krow * KP + n * 8) * 2;
                uint32_t bh0, bh1, bl0, bl1;
                ldmx2t(bh0, bh1, vh_b + off);
                ldmx2t(bl0, bl1, vl_b + off);
                mma16816(oacc[n], pah, bh0, bh1);
                mma16816(oacc[n], pah, bl0, bl1);
                mma16816(oacc[n], pal, bh0, bh1);
            }
        }
        __syncthreads();   // compute done before next prefetch overwrites buf^1
    }

    // ---- epilogue: normalize + store fp32 ----
    const float il = 1.0f / l_lo;
    const float ih = 1.0f / l_hi;
#pragma unroll
    for (int n = 0; n < 8; n++) {
        int c = n * 8 + qc * 2;
        float2 v0 = make_float2(oacc[n][0] * il, oacc[n][1] * il);
        float2 v1 = make_float2(oacc[n][2] * ih, oacc[n][3] * ih);
        *(float2*)&out[rlo * DHEAD + c] = v0;
        *(float2*)&out[rhi * DHEAD + c] = v1;
    }
}

// ===========================================================================
extern "C" void kernel_launch(void* const* d_in, const int* in_sizes, int n_in,
                              void* d_out, int out_size)
{
    const float* x  = (const float*)d_in[0];
    const float* Wq = (const float*)d_in[1];
    const float* bq = (const float*)d_in[2];
    const float* Wk = (const float*)d_in[3];
    const float* bk = (const float*)d_in[4];
    const float* Wv = (const float*)d_in[5];
    const float* bv = (const float*)d_in[6];
    float* out = (float*)d_out;

    (void)in_sizes; (void)n_in; (void)out_size;

    cudaFuncSetAttribute(qkv_kernel,
                         cudaFuncAttributeMaxDynamicSharedMemorySize, QKV_SMEM_BYTES);
    cudaFuncSetAttribute(attn_kernel,
                         cudaFuncAttributeMaxDynamicSharedMemorySize, ATTN_SMEM_BYTES);

    qkv_kernel<<<dim3(BS_TOT / 64), 128, QKV_SMEM_BYTES>>>(x, Wq, bq, Wk, bk, Wv, bv);
    attn_kernel<<<dim3(SEQ / 128, BATCH), 256, ATTN_SMEM_BYTES>>>(out);
}

// round 8
// speedup vs baseline: 3.0672x; 1.3290x over previous
#include <cuda_runtime.h>
#include <cuda_bf16.h>
#include <cstdint>

// Problem dims
#define BATCH   8
#define SEQ     2048
#define DIN     1024
#define DHEAD   64
#define BS_TOT  (BATCH * SEQ)       // 16384

// Projected q/k/v as split bf16 pairs (val = hi + lo), q pre-scaled by 0.125.
__device__ __nv_bfloat16 g_qh[BS_TOT * DHEAD];
__device__ __nv_bfloat16 g_ql[BS_TOT * DHEAD];
__device__ __nv_bfloat16 g_kh[BS_TOT * DHEAD];
__device__ __nv_bfloat16 g_kl[BS_TOT * DHEAD];
__device__ __nv_bfloat16 g_vh[BS_TOT * DHEAD];
__device__ __nv_bfloat16 g_vl[BS_TOT * DHEAD];

// W (q|k|v concatenated, [k][192]) pre-split to bf16 hi/lo once per launch.
__device__ __nv_bfloat16 g_wh[DIN * 192];
__device__ __nv_bfloat16 g_wl[DIN * 192];

// ---------------------------------------------------------------------------
// PTX helpers (sm_80-era; compile fine at compute_100)
// ---------------------------------------------------------------------------
__device__ __forceinline__ uint32_t smem_u32(const void* p) {
    uint32_t a;
    asm("{ .reg .u64 t; cvta.to.shared.u64 t, %1; cvt.u32.u64 %0, t; }" : "=r"(a) : "l"(p));
    return a;
}
__device__ __forceinline__ void mma16816(float* d, const uint32_t* a,
                                         uint32_t b0, uint32_t b1) {
    asm volatile(
        "mma.sync.aligned.m16n8k16.row.col.f32.bf16.bf16.f32 "
        "{%0,%1,%2,%3}, {%4,%5,%6,%7}, {%8,%9}, {%0,%1,%2,%3};\n"
        : "+f"(d[0]), "+f"(d[1]), "+f"(d[2]), "+f"(d[3])
        : "r"(a[0]), "r"(a[1]), "r"(a[2]), "r"(a[3]), "r"(b0), "r"(b1));
}
__device__ __forceinline__ void ldmx4(uint32_t* r, uint32_t addr) {
    asm volatile("ldmatrix.sync.aligned.m8n8.x4.shared.b16 {%0,%1,%2,%3}, [%4];"
                 : "=r"(r[0]), "=r"(r[1]), "=r"(r[2]), "=r"(r[3]) : "r"(addr));
}
__device__ __forceinline__ void ldmx2t(uint32_t& r0, uint32_t& r1, uint32_t addr) {
    asm volatile("ldmatrix.sync.aligned.m8n8.x2.trans.shared.b16 {%0,%1}, [%2];"
                 : "=r"(r0), "=r"(r1) : "r"(addr));
}
__device__ __forceinline__ void cp16(uint32_t dst, const void* src) {
    asm volatile("cp.async.ca.shared.global [%0], [%1], 16;" :: "r"(dst), "l"(src));
}
__device__ __forceinline__ void cp_commit() {
    asm volatile("cp.async.commit_group;");
}
template <int N> __device__ __forceinline__ void cp_wait() {
    asm volatile("cp.async.wait_group %0;" :: "n"(N));
}
__device__ __forceinline__ uint32_t pack2(float a, float b) {
    __nv_bfloat162 h = __floats2bfloat162_rn(a, b);   // a -> lower 16 bits
    return *(uint32_t*)&h;
}
__device__ __forceinline__ void split4(float4 v, uint2& hi, uint2& lo) {
    uint32_t h01 = pack2(v.x, v.y), h23 = pack2(v.z, v.w);
    float2 f01 = __bfloat1622float2(*(__nv_bfloat162*)&h01);
    float2 f23 = __bfloat1622float2(*(__nv_bfloat162*)&h23);
    hi.x = h01; hi.y = h23;
    lo.x = pack2(v.x - f01.x, v.y - f01.y);
    lo.y = pack2(v.z - f23.x, v.w - f23.y);
}

// ===========================================================================
// W pre-split: [1024][192] fp32 (q|k|v) -> bf16 hi/lo. 192 blocks x 256 thr.
// ===========================================================================
__global__ __launch_bounds__(256) void wsplit_kernel(
    const float* __restrict__ Wq, const float* __restrict__ Wk,
    const float* __restrict__ Wv)
{
    int i  = blockIdx.x * 256 + threadIdx.x;   // 0..49151
    int k  = i / 48;
    int c4 = (i % 48) * 4;                     // 0..188 step 4
    int arr = c4 >> 6;
    int cc  = c4 & 63;
    const float* W = (arr == 0) ? Wq : (arr == 1) ? Wk : Wv;
    float4 v = *(const float4*)&W[k * DHEAD + cc];
    uint2 hi, lo; split4(v, hi, lo);
    *(uint2*)&g_wh[k * 192 + c4] = hi;
    *(uint2*)&g_wl[k * 192 + c4] = lo;
}

// ===========================================================================
// Fused QKV projection (mma.sync split-bf16, 3-pass hh+hl+lh).
// Structure = R6's passing kernel; ONLY change: W staged via cp.async from
// pre-split bf16 (no per-chunk fp32 reload/convert), A-frags hoisted and
// f-outer loop order (same proven ldmx2t addressing, half the ldmatrix count).
// 256 CTAs x 128 thr; 64 rows/CTA; warp w: rows 16w..16w+15, all 192 cols.
// ===========================================================================
#define XP   72          // X smem pitch (elems)
#define WPIT 200         // W smem pitch (elems)
#define QKV_XH 0
#define QKV_XL 4608      // 64*72
#define QKV_WH 9216
#define QKV_WL 22016     // 9216 + 64*200
#define QKV_SMEM_BYTES ((22016 + 12800) * 2)   // 69632

__global__ __launch_bounds__(128, 2) void qkv_kernel(
    const float* __restrict__ x,
    const float* __restrict__ bq, const float* __restrict__ bk,
    const float* __restrict__ bv)
{
    extern __shared__ __nv_bfloat16 smq[];
    const uint32_t sbase = smem_u32(smq);

    const int t    = threadIdx.x;
    const int w    = t >> 5;
    const int lane = t & 31;
    const int g    = lane >> 2;
    const int qc   = lane & 3;
    const int m0   = blockIdx.x * 64;
    const int wm   = w * 16;

    float acc[24][4];
#pragma unroll
    for (int f = 0; f < 24; f++)
#pragma unroll
        for (int j = 0; j < 4; j++) acc[f][j] = 0.0f;

    const int srow = t >> 1;

    for (int k0 = 0; k0 < DIN; k0 += 64) {
        // ---- issue W chunk cp.async (pre-split bf16, no convert) ----
#pragma unroll
        for (int j = 0; j < 12; j++) {
            int i   = t + j * 128;               // 0..1535
            int r   = i / 24;                    // 0..63
            int seg = (i % 24) * 8;              // 0..184
            const int go = (k0 + r) * 192 + seg;
            cp16(sbase + (uint32_t)(QKV_WH + r * WPIT + seg) * 2, g_wh + go);
            cp16(sbase + (uint32_t)(QKV_WL + r * WPIT + seg) * 2, g_wl + go);
        }
        cp_commit();

        // ---- stage X chunk [64 rows x 64 k] as hi/lo (overlaps cp latency) ----
        {
            int ks = (t & 1) * 32;
            const float* xr = &x[(m0 + srow) * DIN + k0 + ks];
#pragma unroll
            for (int j = 0; j < 8; j++) {
                float4 v4 = *(const float4*)&xr[j * 4];
                uint2 hi, lo; split4(v4, hi, lo);
                int eo = srow * XP + ks + j * 4;
                *(uint2*)&smq[QKV_XH + eo] = hi;
                *(uint2*)&smq[QKV_XL + eo] = lo;
            }
        }
        cp_wait<0>();
        __syncthreads();

        // ---- A-frags for all 4 k-tiles (hoisted; same addressing as R6) ----
        uint32_t ah[4][4], al[4][4];
        const int ar = wm + (lane & 7) + ((lane >> 3) & 1) * 8;
#pragma unroll
        for (int k4 = 0; k4 < 4; k4++) {
            int ac = k4 * 16 + (lane >> 4) * 8;
            ldmx4(ah[k4], sbase + (uint32_t)(QKV_XH + ar * XP + ac) * 2);
            ldmx4(al[k4], sbase + (uint32_t)(QKV_XL + ar * XP + ac) * 2);
        }

        // ---- f-outer: per fragment 8 ldmx2t + 12 MMAs (R6 addressing) ----
#pragma unroll
        for (int f = 0; f < 24; f++) {
#pragma unroll
            for (int k4 = 0; k4 < 4; k4++) {
                int krow = k4 * 16 + (lane & 15);
                uint32_t baddr = (uint32_t)(krow * WPIT + f * 8) * 2;
                uint32_t bh0, bh1, bl0, bl1;
                ldmx2t(bh0, bh1, sbase + (uint32_t)QKV_WH * 2 + baddr);
                ldmx2t(bl0, bl1, sbase + (uint32_t)QKV_WL * 2 + baddr);
                mma16816(acc[f], ah[k4], bh0, bh1);
                mma16816(acc[f], ah[k4], bl0, bl1);
                mma16816(acc[f], al[k4], bh0, bh1);
            }
        }
        __syncthreads();
    }

    // ---- epilogue: bias + scale, split to bf16 hi/lo, store ----
    const int rl = m0 + wm + g;
    const int rh = rl + 8;
#pragma unroll
    for (int f = 0; f < 24; f++) {
        int c   = f * 8 + 2 * qc;
        int arr = c >> 6;
        int cc  = c & 63;
        const float* ba = (arr == 0) ? bq : (arr == 1) ? bk : bv;
        __nv_bfloat16* oh = (arr == 0) ? g_qh : (arr == 1) ? g_kh : g_vh;
        __nv_bfloat16* ol = (arr == 0) ? g_ql : (arr == 1) ? g_kl : g_vl;
        float s  = (arr == 0) ? 0.125f : 1.0f;
        float b0 = ba[cc], b1 = ba[cc + 1];
        float v0 = (acc[f][0] + b0) * s, v1 = (acc[f][1] + b1) * s;
        float v2 = (acc[f][2] + b0) * s, v3 = (acc[f][3] + b1) * s;
        uint32_t h01 = pack2(v0, v1);
        uint32_t h23 = pack2(v2, v3);
        float2 f01 = __bfloat1622float2(*(__nv_bfloat162*)&h01);
        float2 f23 = __bfloat1622float2(*(__nv_bfloat162*)&h23);
        *(uint32_t*)&oh[rl * DHEAD + cc] = h01;
        *(uint32_t*)&ol[rl * DHEAD + cc] = pack2(v0 - f01.x, v1 - f01.y);
        *(uint32_t*)&oh[rh * DHEAD + cc] = h23;
        *(uint32_t*)&ol[rh * DHEAD + cc] = pack2(v2 - f23.x, v3 - f23.y);
    }
}

// ===========================================================================
// Flash attention — BYTE-IDENTICAL to the R6 passing kernel (100us).
// mma.sync split-bf16 (3-pass), cp.async double-buffered KV.
// Br=128 q-rows/CTA (8 warps x 16), Bc=64 keys/tile, grid 128.
// ===========================================================================
#define KP 72
#define TILE_ELEMS (64 * KP)               // 4608
#define ABASE(arr, buf) (((arr) * 2 + (buf)) * TILE_ELEMS)
#define ATTN_SMEM_BYTES (8 * TILE_ELEMS * 2)   // 73728

__global__ __launch_bounds__(256) void attn_kernel(float* __restrict__ out)
{
    extern __shared__ __nv_bfloat16 sma[];
    const uint32_t sbase = smem_u32(sma);

    const int t    = threadIdx.x;
    const int w    = t >> 5;
    const int lane = t & 31;
    const int g    = lane >> 2;
    const int qc   = lane & 3;

    const int qt = blockIdx.x;             // 0..15
    const int b  = blockIdx.y;             // 0..7
    const int qrow0  = b * SEQ + qt * 128;
    const int kvbase = b * SEQ;

    const int rlo = qrow0 + 16 * w + g;
    const int rhi = rlo + 8;

    const __nv_bfloat16* gsrc[4] = {g_kh, g_kl, g_vh, g_vl};

    // issue tile 0 loads into buf 0
#pragma unroll
    for (int arr = 0; arr < 4; arr++) {
#pragma unroll
        for (int rep = 0; rep < 2; rep++) {
            int i   = t + rep * 256;   // 0..511
            int r   = i >> 3;
            int seg = (i & 7) * 8;
            cp16(sbase + (uint32_t)(ABASE(arr, 0) + r * KP + seg) * 2,
                 gsrc[arr] + (kvbase + r) * DHEAD + seg);
        }
    }
    cp_commit();

    // ---- Q fragments once (warp-invariant across KV tiles) ----
    uint32_t qh[4][4], ql[4][4];
#pragma unroll
    for (int k4 = 0; k4 < 4; k4++) {
        int c = k4 * 16 + qc * 2;
        qh[k4][0] = *(const uint32_t*)&g_qh[rlo * DHEAD + c];
        qh[k4][1] = *(const uint32_t*)&g_qh[rhi * DHEAD + c];
        qh[k4][2] = *(const uint32_t*)&g_qh[rlo * DHEAD + c + 8];
        qh[k4][3] = *(const uint32_t*)&g_qh[rhi * DHEAD + c + 8];
        ql[k4][0] = *(const uint32_t*)&g_ql[rlo * DHEAD + c];
        ql[k4][1] = *(const uint32_t*)&g_ql[rhi * DHEAD + c];
        ql[k4][2] = *(const uint32_t*)&g_ql[rlo * DHEAD + c + 8];
        ql[k4][3] = *(const uint32_t*)&g_ql[rhi * DHEAD + c + 8];
    }

    float m_lo = -3.0e38f, m_hi = -3.0e38f, l_lo = 0.0f, l_hi = 0.0f;
    float oacc[8][4];
#pragma unroll
    for (int n = 0; n < 8; n++)
#pragma unroll
        for (int j = 0; j < 4; j++) oacc[n][j] = 0.0f;

    for (int kt = 0; kt < SEQ / 64; kt++) {
        const int buf = kt & 1;

        // prefetch next tile into the other buffer
        if (kt < SEQ / 64 - 1) {
            const int nb = buf ^ 1;
            const int krow0 = kvbase + (kt + 1) * 64;
#pragma unroll
            for (int arr = 0; arr < 4; arr++) {
#pragma unroll
                for (int rep = 0; rep < 2; rep++) {
                    int i   = t + rep * 256;
                    int r   = i >> 3;
                    int seg = (i & 7) * 8;
                    cp16(sbase + (uint32_t)(ABASE(arr, nb) + r * KP + seg) * 2,
                         gsrc[arr] + (krow0 + r) * DHEAD + seg);
                }
            }
            cp_commit();
            cp_wait<1>();
        } else {
            cp_wait<0>();
        }
        __syncthreads();

        const __nv_bfloat16* Kh = sma + ABASE(0, buf);
        const __nv_bfloat16* Kl = sma + ABASE(1, buf);
        const uint32_t vh_b = sbase + (uint32_t)ABASE(2, buf) * 2;
        const uint32_t vl_b = sbase + (uint32_t)ABASE(3, buf) * 2;

        // ---- S = Q K^T (3-pass split) ----
        float sacc[8][4];
#pragma unroll
        for (int n = 0; n < 8; n++)
#pragma unroll
            for (int j = 0; j < 4; j++) sacc[n][j] = 0.0f;

#pragma unroll
        for (int k4 = 0; k4 < 4; k4++) {
#pragma unroll
            for (int n = 0; n < 8; n++) {
                int base = (n * 8 + g) * KP + k4 * 16 + qc * 2;
                uint32_t bh0 = *(const uint32_t*)&Kh[base];
                uint32_t bh1 = *(const uint32_t*)&Kh[base + 8];
                uint32_t bl0 = *(const uint32_t*)&Kl[base];
                uint32_t bl1 = *(const uint32_t*)&Kl[base + 8];
                mma16816(sacc[n], qh[k4], bh0, bh1);
                mma16816(sacc[n], qh[k4], bl0, bl1);
                mma16816(sacc[n], ql[k4], bh0, bh1);
            }
        }

        // ---- online softmax (rows rlo: c0/c1, rhi: c2/c3) ----
        float tl = -3.0e38f, th = -3.0e38f;
#pragma unroll
        for (int n = 0; n < 8; n++) {
            tl = fmaxf(tl, fmaxf(sacc[n][0], sacc[n][1]));
            th = fmaxf(th, fmaxf(sacc[n][2], sacc[n][3]));
        }
        tl = fmaxf(tl, __shfl_xor_sync(0xffffffffu, tl, 1));
        tl = fmaxf(tl, __shfl_xor_sync(0xffffffffu, tl, 2));
        th = fmaxf(th, __shfl_xor_sync(0xffffffffu, th, 1));
        th = fmaxf(th, __shfl_xor_sync(0xffffffffu, th, 2));

        float mn_lo = fmaxf(m_lo, tl);
        float mn_hi = fmaxf(m_hi, th);
        float al_lo = __expf(m_lo - mn_lo);
        float al_hi = __expf(m_hi - mn_hi);
        m_lo = mn_lo; m_hi = mn_hi;

        float slo = 0.0f, shi = 0.0f;
#pragma unroll
        for (int n = 0; n < 8; n++) {
            float e0 = __expf(sacc[n][0] - mn_lo);
            float e1 = __expf(sacc[n][1] - mn_lo);
            float e2 = __expf(sacc[n][2] - mn_hi);
            float e3 = __expf(sacc[n][3] - mn_hi);
            sacc[n][0] = e0; sacc[n][1] = e1; sacc[n][2] = e2; sacc[n][3] = e3;
            slo += e0 + e1; shi += e2 + e3;
        }
        slo += __shfl_xor_sync(0xffffffffu, slo, 1);
        slo += __shfl_xor_sync(0xffffffffu, slo, 2);
        shi += __shfl_xor_sync(0xffffffffu, shi, 1);
        shi += __shfl_xor_sync(0xffffffffu, shi, 2);
        l_lo = l_lo * al_lo + slo;
        l_hi = l_hi * al_hi + shi;

#pragma unroll
        for (int n = 0; n < 8; n++) {
            oacc[n][0] *= al_lo; oacc[n][1] *= al_lo;
            oacc[n][2] *= al_hi; oacc[n][3] *= al_hi;
        }

        // ---- PV: O += P V (P frags in regs; V B-frags via ldmatrix.trans) ----
#pragma unroll
        for (int pk = 0; pk < 4; pk++) {
            uint32_t pah[4], pal[4];
#pragma unroll
            for (int half = 0; half < 2; half++) {
                float e0 = sacc[2 * pk + half][0];
                float e1 = sacc[2 * pk + half][1];
                float e2 = sacc[2 * pk + half][2];
                float e3 = sacc[2 * pk + half][3];
                uint32_t h01 = pack2(e0, e1);
                uint32_t h23 = pack2(e2, e3);
                float2 f01 = __bfloat1622float2(*(__nv_bfloat162*)&h01);
                float2 f23 = __bfloat1622float2(*(__nv_bfloat162*)&h23);
                pah[0 + 2 * half] = h01;
                pah[1 + 2 * half] = h23;
                pal[0 + 2 * half] = pack2(e0 - f01.x, e1 - f01.y);
                pal[1 + 2 * half] = pack2(e2 - f23.x, e3 - f23.y);
            }
            const uint32_t krow = (uint32_t)(pk * 16 + (lane & 15));
#pragma unroll
            for (int n = 0; n < 8; n++) {
                uint32_t off = (krow * KP + n * 8) * 2;
                uint32_t bh0, bh1, bl0, bl1;
                ldmx2t(bh0, bh1, vh_b + off);
                ldmx2t(bl0, bl1, vl_b + off);
                mma16816(oacc[n], pah, bh0, bh1);
                mma16816(oacc[n], pah, bl0, bl1);
                mma16816(oacc[n], pal, bh0, bh1);
            }
        }
        __syncthreads();   // compute done before next prefetch overwrites buf^1
    }

    // ---- epilogue: normalize + store fp32 ----
    const float il = 1.0f / l_lo;
    const float ih = 1.0f / l_hi;
#pragma unroll
    for (int n = 0; n < 8; n++) {
        int c = n * 8 + qc * 2;
        float2 v0 = make_float2(oacc[n][0] * il, oacc[n][1] * il);
        float2 v1 = make_float2(oacc[n][2] * ih, oacc[n][3] * ih);
        *(float2*)&out[rlo * DHEAD + c] = v0;
        *(float2*)&out[rhi * DHEAD + c] = v1;
    }
}

// ===========================================================================
extern "C" void kernel_launch(void* const* d_in, const int* in_sizes, int n_in,
                              void* d_out, int out_size)
{
    const float* x  = (const float*)d_in[0];
    const float* Wq = (const float*)d_in[1];
    const float* bq = (const float*)d_in[2];
    const float* Wk = (const float*)d_in[3];
    const float* bk = (const float*)d_in[4];
    const float* Wv = (const float*)d_in[5];
    const float* bv = (const float*)d_in[6];
    float* out = (float*)d_out;

    (void)in_sizes; (void)n_in; (void)out_size;

    cudaFuncSetAttribute(qkv_kernel,
                         cudaFuncAttributeMaxDynamicSharedMemorySize, QKV_SMEM_BYTES);
    cudaFuncSetAttribute(attn_kernel,
                         cudaFuncAttributeMaxDynamicSharedMemorySize, ATTN_SMEM_BYTES);

    wsplit_kernel<<<192, 256>>>(Wq, Wk, Wv);
    qkv_kernel<<<dim3(BS_TOT / 64), 128, QKV_SMEM_BYTES>>>(x, bq, bk, bv);
    attn_kernel<<<dim3(SEQ / 128, BATCH), 256, ATTN_SMEM_BYTES>>>(out);
}